// round 1
// baseline (speedup 1.0000x reference)
#include <cuda_runtime.h>
#include <math.h>
#include <stdint.h>

// ---------------------------------------------------------------------------
// Problem constants (capacities; runtime sizes read from in_sizes/out_size)
// ---------------------------------------------------------------------------
#define EMAX 250000
#define NMAX 25000

// constants
#define INV_NN   0.51298917604257706f   // 1/sqrt(3.8)
#define INV3     0.57735026918962576f   // 1/sqrt(3)
#define INV112   0.89285714285714285f   // 1/1.12
#define S3       1.7320508075688772f
#define S5       2.2360679774997896f
#define S7       2.6457513110645907f
#define S15      3.8729833462074170f
#define S105     10.246950765959598f
#define C358     2.0916500663351889f    // sqrt(35/8)
#define C218     1.6201851746019651f    // sqrt(21/8)
#define RS3      0.57735026918962576f   // 1/sqrt(3)
#define RS5      0.44721359549995794f   // 1/sqrt(5)
#define RS7      0.37796447300922720f   // 1/sqrt(7)
#define SCALE1   (INV3 * 0.5f / 16.0f * INV_NN)   // h1-norm * ef*0.5 * mlp/16 * segsum
#define SCALE2   (INV3 / 128.0f * INV_NN)          // h2-norm * /16 * /8 * segsum

// ---------------------------------------------------------------------------
// Scratch (static device arrays; no allocations anywhere)
// ---------------------------------------------------------------------------
__device__ float g_sh  [EMAX * 16];     // spherical harmonics per edge
__device__ float g_x   [NMAX * 16];     // raw segment sum of sh per node
__device__ float g_dots[EMAX * 4];      // per-edge dots (inv_nn folded in)
__device__ int   g_hist[NMAX];
__device__ int   g_off [NMAX + 1];
__device__ int   g_cur [NMAX];
__device__ int   g_perm[EMAX];
__device__ float g_T   [(size_t)NMAX * 1024];  // per-node outer-product accum [c*4+p]
__device__ float g_Wre [1024 * 96];     // W1b reordered: [(c*4+p), k]
__device__ float g_h   [NMAX * 96];     // node features after stage-1 GEMM
__device__ float g_z   [(size_t)NMAX * 256];   // z = W2b @ y per node

// ---------------------------------------------------------------------------
// K0: zero accumulators and output
// ---------------------------------------------------------------------------
__global__ void k_zero(float* __restrict__ out, int N)
{
    int i = blockIdx.x * blockDim.x + threadIdx.x;
    if (i < N * 16) g_x[i] = 0.f;
    if (i < N) { g_hist[i] = 0; out[i] = 0.f; }
}

// ---------------------------------------------------------------------------
// K1: spherical harmonics, x segment-sum (atomic), dst histogram
// ---------------------------------------------------------------------------
__global__ void k_sh(const float* __restrict__ edge_vec,
                     const int*   __restrict__ edst, int E)
{
    int e = blockIdx.x * blockDim.x + threadIdx.x;
    if (e >= E) return;
    float x = edge_vec[e * 3 + 0];
    float y = edge_vec[e * 3 + 1];
    float z = edge_vec[e * 3 + 2];
    float nrm = sqrtf(x * x + y * y + z * z);
    float inv = 1.0f / (nrm + 1e-12f);
    x *= inv; y *= inv; z *= inv;
    float x2 = x * x, y2 = y * y, z2 = z * z;

    float sh[16];
    sh[0]  = 1.0f;
    sh[1]  = S3 * x;
    sh[2]  = S3 * y;
    sh[3]  = S3 * z;
    sh[4]  = S15 * x * z;
    sh[5]  = S15 * x * y;
    sh[6]  = 0.5f * S5 * (2.0f * y2 - x2 - z2);
    sh[7]  = S15 * y * z;
    sh[8]  = 0.5f * S15 * (z2 - x2);
    sh[9]  = C358 * x * (3.0f * z2 - x2);
    sh[10] = S105 * x * y * z;
    sh[11] = C218 * x * (4.0f * y2 - z2 - x2);
    sh[12] = 0.5f * S7 * y * (2.0f * y2 - 3.0f * z2 - 3.0f * x2);
    sh[13] = C218 * z * (4.0f * y2 - z2 - x2);
    sh[14] = 0.5f * S105 * y * (z2 - x2);
    sh[15] = C358 * z * (z2 - 3.0f * x2);

    float4* shp = (float4*)&g_sh[(size_t)e * 16];
    shp[0] = make_float4(sh[0], sh[1], sh[2], sh[3]);
    shp[1] = make_float4(sh[4], sh[5], sh[6], sh[7]);
    shp[2] = make_float4(sh[8], sh[9], sh[10], sh[11]);
    shp[3] = make_float4(sh[12], sh[13], sh[14], sh[15]);

    int d = edst[e];
    float* xp = &g_x[(size_t)d * 16];
#pragma unroll
    for (int i = 0; i < 16; i++) atomicAdd(&xp[i], sh[i]);
    atomicAdd(&g_hist[d], 1);
}

// ---------------------------------------------------------------------------
// K2: exclusive scan of histogram (single block, warp-scan based)
// ---------------------------------------------------------------------------
__global__ void __launch_bounds__(1024) k_scan(int E, int N)
{
    __shared__ int wsum[32];
    __shared__ int wpre[32];
    int tid = threadIdx.x;
    int lane = tid & 31, wid = tid >> 5;
    int carry = 0;
    for (int base = 0; base < N; base += 1024) {
        int i = base + tid;
        int v = (i < N) ? g_hist[i] : 0;
        // warp inclusive scan
        int xv = v;
#pragma unroll
        for (int o = 1; o < 32; o <<= 1) {
            int t = __shfl_up_sync(0xffffffffu, xv, o);
            if (lane >= o) xv += t;
        }
        if (lane == 31) wsum[wid] = xv;
        __syncthreads();
        if (wid == 0) {
            int wv = wsum[lane];
            int xs = wv;
#pragma unroll
            for (int o = 1; o < 32; o <<= 1) {
                int t = __shfl_up_sync(0xffffffffu, xs, o);
                if (lane >= o) xs += t;
            }
            wpre[lane] = xs - wv;
        }
        __syncthreads();
        int incl = xv + wpre[wid];
        int excl = incl - v + carry;
        if (i < N) { g_off[i] = excl; g_cur[i] = excl; }
        carry += wpre[31] + wsum[31];
        __syncthreads();
    }
    if (tid == 0) g_off[N] = E;
}

// ---------------------------------------------------------------------------
// K2b: reorder W1b [256,384] -> Wre [(c*4+p), k] with k in [0,96)
// ---------------------------------------------------------------------------
__global__ void k_reord(const float* __restrict__ W1b)
{
    int idx = blockIdx.x * blockDim.x + threadIdx.x;
    if (idx >= 1024 * 96) return;
    int kk = idx / 96;        // c*4+p
    int k  = idx - kk * 96;
    int c  = kk >> 2;
    int p  = kk & 3;
    g_Wre[idx] = W1b[c * 384 + p * 96 + k];
}

// ---------------------------------------------------------------------------
// K3: dots per edge + permutation scatter (counting-sort placement)
// ---------------------------------------------------------------------------
__global__ void k_dots(const int* __restrict__ esrc,
                       const int* __restrict__ edst, int E)
{
    int e = blockIdx.x * blockDim.x + threadIdx.x;
    if (e >= E) return;
    int src = esrc[e];
    int dst = edst[e];
    const float4* shp = (const float4*)&g_sh[(size_t)e * 16];
    const float4* xp  = (const float4*)&g_x[(size_t)src * 16];
    float4 s0 = shp[0], s1 = shp[1], s2 = shp[2], s3 = shp[3];
    float4 x0 = xp[0],  x1 = xp[1],  x2 = xp[2],  x3 = xp[3];

    float d0 = x0.x * s0.x;
    float d1 = (x0.y * s0.y + x0.z * s0.z + x0.w * s0.w) * RS3;
    float d2 = (x1.x * s1.x + x1.y * s1.y + x1.z * s1.z + x1.w * s1.w + x2.x * s2.x) * RS5;
    float d3 = (x2.y * s2.y + x2.z * s2.z + x2.w * s2.w +
                x3.x * s3.x + x3.y * s3.y + x3.z * s3.z + x3.w * s3.w) * RS7;

    *(float4*)&g_dots[(size_t)e * 4] =
        make_float4(d0 * INV_NN, d1 * INV_NN, d2 * INV_NN, d3 * INV_NN);

    int pos = atomicAdd(&g_cur[dst], 1);
    g_perm[pos] = e;
}

// ---------------------------------------------------------------------------
// K4: build T[n, c*4+p] = sum_{e->n} relu(basis_e . W1a[:,c]) * dots[e,p]
//     one warp per node; lane owns c = j*32+lane for j in 0..7
// ---------------------------------------------------------------------------
__global__ void __launch_bounds__(256) k_buildT(const float* __restrict__ edge_len,
                                                const float* __restrict__ W1a, int N)
{
    __shared__ float sW[768];
    for (int i = threadIdx.x; i < 768; i += 256) sW[i] = W1a[i];
    __syncthreads();

    int w = blockIdx.x * 8 + (threadIdx.x >> 5);
    int lane = threadIdx.x & 31;
    if (w >= N) return;
    int beg = g_off[w], end = g_off[w + 1];

    float wa0[8], wa1[8], wa2[8];
#pragma unroll
    for (int j = 0; j < 8; j++) {
        int c = j * 32 + lane;
        wa0[j] = sW[c]; wa1[j] = sW[256 + c]; wa2[j] = sW[512 + c];
    }
    float4 acc[8];
#pragma unroll
    for (int j = 0; j < 8; j++) acc[j] = make_float4(0.f, 0.f, 0.f, 0.f);

    for (int i = beg; i < end; i++) {
        int e = g_perm[i];
        float len = edge_len[e];
        float t0 = len * 0.5f;
        float t1 = (len - 2.0f) * 0.5f;
        float t2 = (len - 4.0f) * 0.5f;
        float b0 = expf(-t0 * t0) * INV112;
        float b1 = expf(-t1 * t1) * INV112;
        float b2 = expf(-t2 * t2) * INV112;
        float4 dt = *(const float4*)&g_dots[(size_t)e * 4];
#pragma unroll
        for (int j = 0; j < 8; j++) {
            float h1 = fmaxf(fmaf(b0, wa0[j], fmaf(b1, wa1[j], b2 * wa2[j])), 0.f);
            acc[j].x = fmaf(h1, dt.x, acc[j].x);
            acc[j].y = fmaf(h1, dt.y, acc[j].y);
            acc[j].z = fmaf(h1, dt.z, acc[j].z);
            acc[j].w = fmaf(h1, dt.w, acc[j].w);
        }
    }
    float* tp = &g_T[(size_t)w * 1024];
#pragma unroll
    for (int j = 0; j < 8; j++)
        *(float4*)&tp[(j * 32 + lane) * 4] = acc[j];
}

// ---------------------------------------------------------------------------
// K5: node GEMM h = T @ Wre * SCALE1 :  [N,1024] @ [1024,96]
//     64x96 CTA tile, 128 threads, 8x6 register blocking, BK=16
// ---------------------------------------------------------------------------
__global__ void __launch_bounds__(128) k_gemm(int M)
{
    __shared__ float As[16][68];   // [k][m]
    __shared__ float Bs[16][100];  // [k][n]
    int tid = threadIdx.x;
    int m0 = blockIdx.x * 64;
    int cg = tid & 15;   // 16 col groups x 6 cols
    int rg = tid >> 4;   // 8 row groups x 8 rows

    float acc[8][6];
#pragma unroll
    for (int i = 0; i < 8; i++)
#pragma unroll
        for (int j = 0; j < 6; j++) acc[i][j] = 0.f;

    for (int kc = 0; kc < 1024; kc += 16) {
        // load A tile (transposed into smem)
#pragma unroll
        for (int q = tid; q < 256; q += 128) {
            int row = q >> 2;
            int kq = (q & 3) << 2;
            int gm = m0 + row;
            float4 v = make_float4(0.f, 0.f, 0.f, 0.f);
            if (gm < M) v = *(const float4*)&g_T[(size_t)gm * 1024 + kc + kq];
            As[kq + 0][row] = v.x;
            As[kq + 1][row] = v.y;
            As[kq + 2][row] = v.z;
            As[kq + 3][row] = v.w;
        }
        // load B tile
#pragma unroll
        for (int q = tid; q < 1536; q += 128) {
            int r = q / 96;
            int col = q - r * 96;
            Bs[r][col] = g_Wre[(kc + r) * 96 + col];
        }
        __syncthreads();
#pragma unroll
        for (int k = 0; k < 16; k++) {
            float4 a0 = *(const float4*)&As[k][rg * 8];
            float4 a1 = *(const float4*)&As[k][rg * 8 + 4];
            float a[8] = {a0.x, a0.y, a0.z, a0.w, a1.x, a1.y, a1.z, a1.w};
            float b[6];
#pragma unroll
            for (int j = 0; j < 6; j++) b[j] = Bs[k][cg * 6 + j];
#pragma unroll
            for (int i = 0; i < 8; i++)
#pragma unroll
                for (int j = 0; j < 6; j++)
                    acc[i][j] = fmaf(a[i], b[j], acc[i][j]);
        }
        __syncthreads();
    }
#pragma unroll
    for (int i = 0; i < 8; i++) {
        int gm = m0 + rg * 8 + i;
        if (gm < M) {
#pragma unroll
            for (int j = 0; j < 6; j++)
                g_h[(size_t)gm * 96 + cg * 6 + j] = acc[i][j] * SCALE1;
        }
    }
}

// ---------------------------------------------------------------------------
// K6: per-node activation y, then z = W2b @ y   (32 nodes per 256-thread CTA)
// ---------------------------------------------------------------------------
__global__ void __launch_bounds__(256) k_yz(const float* __restrict__ W2b, int N)
{
    __shared__ float sy[32][64];
    int n0 = blockIdx.x * 32;
    int tid = threadIdx.x;

    for (int q = tid; q < 2048; q += 256) {
        int node = q >> 6;
        int k = q & 63;
        int gn = n0 + node;
        float yv = 0.f;
        if (gn < N) {
            const float* hp = &g_h[(size_t)gn * 96];
            if (k < 32) {
                float s = hp[k];
                yv = (k < 16) ? fmaxf(s, 0.f) : fabsf(s);
            } else {
                int j = k - 32;
                float gv = hp[32 + j];
                float vv = hp[64 + j];
                float ga;
                if (j < 8)       ga = fmaxf(gv, 0.f);
                else if (j < 16) ga = tanhf(gv);
                else if (j < 24) ga = fmaxf(gv, 0.f);
                else             ga = tanhf(gv);
                yv = ga * vv;
            }
        }
        sy[node][k] = yv;
    }
    __syncthreads();

    int c = tid;  // 0..255
    float wreg[64];
#pragma unroll
    for (int k4 = 0; k4 < 16; k4++) {
        float4 v = *(const float4*)&W2b[c * 64 + k4 * 4];
        wreg[k4 * 4 + 0] = v.x; wreg[k4 * 4 + 1] = v.y;
        wreg[k4 * 4 + 2] = v.z; wreg[k4 * 4 + 3] = v.w;
    }
    for (int node = 0; node < 32; node++) {
        int gn = n0 + node;
        if (gn >= N) break;
        float s = 0.f;
#pragma unroll
        for (int k = 0; k < 64; k++) s = fmaf(wreg[k], sy[node][k], s);
        g_z[(size_t)gn * 256 + c] = s;
    }
}

// ---------------------------------------------------------------------------
// K7: final edge pass: ef2 = relu(basis@W2a) . z[src] * SCALE2, atomic to out
//     one warp per edge, lane owns c = j*32+lane
// ---------------------------------------------------------------------------
__global__ void __launch_bounds__(256) k_final(const float* __restrict__ edge_len,
                                               const float* __restrict__ W2a,
                                               const int* __restrict__ esrc,
                                               const int* __restrict__ edst,
                                               float* __restrict__ out, int E)
{
    __shared__ float sW[768];
    for (int i = threadIdx.x; i < 768; i += 256) sW[i] = W2a[i];
    __syncthreads();

    int w = blockIdx.x * 8 + (threadIdx.x >> 5);
    int lane = threadIdx.x & 31;
    if (w >= E) return;
    int src = esrc[w];
    int dst = edst[w];
    float len = edge_len[w];
    float t0 = len * 0.5f;
    float t1 = (len - 2.0f) * 0.5f;
    float t2 = (len - 4.0f) * 0.5f;
    float b0 = expf(-t0 * t0) * INV112;
    float b1 = expf(-t1 * t1) * INV112;
    float b2 = expf(-t2 * t2) * INV112;

    const float* zp = &g_z[(size_t)src * 256];
    float sum = 0.f;
#pragma unroll
    for (int j = 0; j < 8; j++) {
        int c = j * 32 + lane;
        float h2 = fmaxf(fmaf(b0, sW[c], fmaf(b1, sW[256 + c], b2 * sW[512 + c])), 0.f);
        sum = fmaf(h2, zp[c], sum);
    }
#pragma unroll
    for (int o = 16; o > 0; o >>= 1)
        sum += __shfl_down_sync(0xffffffffu, sum, o);
    if (lane == 0) atomicAdd(&out[dst], sum * SCALE2);
}

// ---------------------------------------------------------------------------
// Launch
// ---------------------------------------------------------------------------
extern "C" void kernel_launch(void* const* d_in, const int* in_sizes, int n_in,
                              void* d_out, int out_size)
{
    const float* edge_vec = (const float*)d_in[0];
    const float* edge_len = (const float*)d_in[1];
    const float* W1a      = (const float*)d_in[2];
    const float* W1b      = (const float*)d_in[3];
    const float* W2a      = (const float*)d_in[4];
    const float* W2b      = (const float*)d_in[5];
    const int*   esrc     = (const int*)d_in[6];
    const int*   edst     = (const int*)d_in[7];
    float* out = (float*)d_out;

    int E = in_sizes[1];   // edge_len count
    int N = out_size;      // 25000
    if (E > EMAX) E = EMAX;
    if (N > NMAX) N = NMAX;

    k_zero<<<(N * 16 + 255) / 256, 256>>>(out, N);
    k_sh<<<(E + 255) / 256, 256>>>(edge_vec, edst, E);
    k_reord<<<(1024 * 96 + 255) / 256, 256>>>(W1b);
    k_scan<<<1, 1024>>>(E, N);
    k_dots<<<(E + 255) / 256, 256>>>(esrc, edst, E);
    k_buildT<<<(N + 7) / 8, 256>>>(edge_len, W1a, N);
    k_gemm<<<(N + 63) / 64, 128>>>(N);
    k_yz<<<(N + 31) / 32, 256>>>(W2b, N);
    k_final<<<(E + 7) / 8, 256>>>(edge_len, W2a, esrc, edst, out, E);
}